// round 2
// baseline (speedup 1.0000x reference)
#include <cuda_runtime.h>
#include <cuda_bf16.h>
#include <math_constants.h>

// Problem constants
#define B_  4
#define TE_ 1024
#define TD_ 512
#define H_  128

#define DT_ 4       // decoder steps per block (kernel 2)
#define TT_ 32      // encoder-t tile (kernel 2)
#define THREADS2 128

// Scratch for projections
__device__ float g_Ws[B_ * TE_ * H_]; // [B,TE,H]
__device__ float g_Uh[B_ * TD_ * H_]; // [B,TD,H]

__device__ __forceinline__ float tanhfast(float x) {
    float y;
    asm("tanh.approx.f32 %0, %1;" : "=f"(y) : "f"(x));
    return y;
}

// ---------------------------------------------------------------------------
// Kernel 1: projections.  blocks 0..511 -> W_s rows (enc @ W_a),
//                         blocks 512..767 -> U_h rows (dec @ U_a).
// 8 rows per block, 128 threads (one output column per thread).
// ---------------------------------------------------------------------------
__global__ void proj_kernel(const float* __restrict__ enc,
                            const float* __restrict__ dec,
                            const float* __restrict__ Wa,
                            const float* __restrict__ Ua)
{
    __shared__ float xs[8][128];
    const int bid = blockIdx.x;
    const int t   = threadIdx.x;

    const float* x;
    const float* M;
    float*       out;
    int row0;
    if (bid < (B_ * TE_ / 8)) {       // 512 blocks
        row0 = bid * 8;
        x = enc;  M = Wa;  out = g_Ws;
    } else {
        row0 = (bid - (B_ * TE_ / 8)) * 8;
        x = dec;  M = Ua;  out = g_Uh;
    }

#pragma unroll
    for (int r = 0; r < 8; ++r)
        xs[r][t] = x[(size_t)(row0 + r) * H_ + t];
    __syncthreads();

    float acc[8];
#pragma unroll
    for (int r = 0; r < 8; ++r) acc[r] = 0.f;

#pragma unroll 4
    for (int h = 0; h < H_; ++h) {
        const float w = M[h * H_ + t];
#pragma unroll
        for (int r = 0; r < 8; ++r)
            acc[r] = fmaf(xs[r][h], w, acc[r]);
    }

#pragma unroll
    for (int r = 0; r < 8; ++r)
        out[(size_t)(row0 + r) * H_ + t] = acc[r];
}

// ---------------------------------------------------------------------------
// Block-wide reduction helpers (128 threads, 4 warps)
// ---------------------------------------------------------------------------
__device__ __forceinline__ float block_reduce(float v, bool is_max, float* red)
{
#pragma unroll
    for (int o = 16; o > 0; o >>= 1) {
        float other = __shfl_xor_sync(0xffffffffu, v, o);
        v = is_max ? fmaxf(v, other) : (v + other);
    }
    const int warp = threadIdx.x >> 5;
    if ((threadIdx.x & 31) == 0) red[warp] = v;
    __syncthreads();
    float r0 = red[0], r1 = red[1], r2 = red[2], r3 = red[3];
    __syncthreads();
    return is_max ? fmaxf(fmaxf(r0, r1), fmaxf(r2, r3)) : (r0 + r1 + r2 + r3);
}

// ---------------------------------------------------------------------------
// Kernel 2: fused energies + softmax + context.
// Grid: (TD_/DT_, B_).  Block: 128 threads (4 warps).
// Warp w handles decoder step d0+w; lane = one encoder position within a tile.
// ---------------------------------------------------------------------------
__global__ __launch_bounds__(THREADS2)
void attn_kernel(const float* __restrict__ enc,
                 const float* __restrict__ Va,
                 float* __restrict__ c_out,  // [B,TD,H]
                 float* __restrict__ e_out)  // [B,TD,TE]
{
    // padded to 33 float4 per row: start bank = 4*(lane+q) mod 32 -> conflict free
    __shared__ float4 ws4[TT_ * 33];            // 16896 B (also reused for enc tiles)
    __shared__ float4 uh4[DT_ * 32];            //  2048 B
    __shared__ float4 v4s[32];                  //   512 B
    __shared__ float  es[DT_ * TE_];            // 16384 B
    __shared__ float  red[4];

    const int b    = blockIdx.y;
    const int d0   = blockIdx.x * DT_;
    const int tid  = threadIdx.x;
    const int lane = tid & 31;
    const int warp = tid >> 5;

    // stage U_h rows and V
    {
        const float4* uh_src = (const float4*)(g_Uh + ((size_t)b * TD_ + d0) * H_);
        uh4[tid] = uh_src[tid];                 // 128 float4 = DT_*32
        if (tid < 32) v4s[tid] = ((const float4*)Va)[tid];
    }

    // ----- Phase A: energies -----
    const int n_tiles = TE_ / TT_;
    for (int tile = 0; tile < n_tiles; ++tile) {
        __syncthreads();
        // stage Ws rows [tile*TT_, +TT_)
        const float4* src = (const float4*)(g_Ws + ((size_t)b * TE_ + tile * TT_) * H_);
#pragma unroll
        for (int i = 0; i < (TT_ * 32) / THREADS2; ++i) {
            int f = tid + i * THREADS2;
            int r = f >> 5, q = f & 31;
            ws4[r * 33 + q] = src[f];
        }
        __syncthreads();

        // warp 'warp' -> decoder step d0+warp, lane -> t = tile*TT_ + lane
        float acc = 0.f;
#pragma unroll 8
        for (int q = 0; q < 32; ++q) {
            const float4 wv = ws4[lane * 33 + q];
            const float4 uv = uh4[warp * 32 + q];
            const float4 vv = v4s[q];
            acc = fmaf(vv.x, tanhfast(wv.x + uv.x), acc);
            acc = fmaf(vv.y, tanhfast(wv.y + uv.y), acc);
            acc = fmaf(vv.z, tanhfast(wv.z + uv.z), acc);
            acc = fmaf(vv.w, tanhfast(wv.w + uv.w), acc);
        }
        es[warp * TE_ + tile * TT_ + lane] = acc;
    }
    __syncthreads();

    // ----- Phase B: softmax over TE per decoder step -----
    for (int dd = 0; dd < DT_; ++dd) {
        float m = -CUDART_INF_F;
        for (int i = tid; i < TE_; i += THREADS2)
            m = fmaxf(m, es[dd * TE_ + i]);
        m = block_reduce(m, true, red);

        float s = 0.f;
        for (int i = tid; i < TE_; i += THREADS2) {
            float ex = __expf(es[dd * TE_ + i] - m);
            es[dd * TE_ + i] = ex;
            s += ex;
        }
        s = block_reduce(s, false, red);
        const float inv = 1.f / s;

        float* eo = e_out + ((size_t)b * TD_ + d0 + dd) * TE_;
        for (int i = tid; i < TE_; i += THREADS2) {
            float p = es[dd * TE_ + i] * inv;
            es[dd * TE_ + i] = p;
            eo[i] = p;
        }
        __syncthreads();
    }

    // ----- Phase C: context c[b,d,:] = sum_t e[t] * enc[b,t,:] -----
    // thread owns (dd = warp, float4 of H at hq = lane)
    float4 acc4 = make_float4(0.f, 0.f, 0.f, 0.f);
    const int dd = warp;
    const int hq = lane;

    for (int tile = 0; tile < n_tiles; ++tile) {
        __syncthreads();
        const float4* src = (const float4*)(enc + ((size_t)b * TE_ + tile * TT_) * H_);
#pragma unroll
        for (int i = 0; i < (TT_ * 32) / THREADS2; ++i) {
            int f = tid + i * THREADS2;
            int r = f >> 5, q = f & 31;
            ws4[r * 33 + q] = src[f];
        }
        __syncthreads();

#pragma unroll 8
        for (int r = 0; r < TT_; ++r) {
            const float  w  = es[dd * TE_ + tile * TT_ + r];   // warp broadcast
            const float4 ev = ws4[r * 33 + hq];                // contiguous lanes
            acc4.x = fmaf(w, ev.x, acc4.x);
            acc4.y = fmaf(w, ev.y, acc4.y);
            acc4.z = fmaf(w, ev.z, acc4.z);
            acc4.w = fmaf(w, ev.w, acc4.w);
        }
    }

    float4* co = (float4*)(c_out + ((size_t)b * TD_ + d0 + dd) * H_);
    co[hq] = acc4;
}

// ---------------------------------------------------------------------------
extern "C" void kernel_launch(void* const* d_in, const int* in_sizes, int n_in,
                              void* d_out, int out_size)
{
    const float* enc = (const float*)d_in[0];   // [B,TE,H]
    const float* dec = (const float*)d_in[1];   // [B,TD,H]
    const float* Wa  = (const float*)d_in[2];   // [H,H]
    const float* Ua  = (const float*)d_in[3];   // [H,H]
    const float* Va  = (const float*)d_in[4];   // [H,1]

    float* c_out = (float*)d_out;                       // [B,TD,H]
    float* e_out = c_out + (size_t)B_ * TD_ * H_;       // [B,TD,TE]

    // projections: 512 blocks for Ws + 256 for Uh
    proj_kernel<<<(B_ * TE_ / 8) + (B_ * TD_ / 8), 128>>>(enc, dec, Wa, Ua);

    dim3 grid(TD_ / DT_, B_);
    attn_kernel<<<grid, THREADS2>>>(enc, Va, c_out, e_out);
}

// round 3
// speedup vs baseline: 1.0856x; 1.0856x over previous
#include <cuda_runtime.h>
#include <cuda_bf16.h>
#include <math_constants.h>

// Problem constants
#define B_  4
#define TE_ 1024
#define TD_ 512
#define H_  128

#define DT_ 4        // decoder steps per block
#define TT_ 64       // encoder-t tile rows (staged in smem)
#define THREADS2 256 // 8 warps: 2 warps per decoder step

// Scratch for projections
__device__ float g_Ws[B_ * TE_ * H_]; // [B,TE,H]
__device__ float g_Uh[B_ * TD_ * H_]; // [B,TD,H]

__device__ __forceinline__ float tanhfast(float x) {
    float y;
    asm("tanh.approx.f32 %0, %1;" : "=f"(y) : "f"(x));
    return y;
}

// ---------------------------------------------------------------------------
// Kernel 1: projections.  blocks 0..511 -> W_s rows (enc @ W_a),
//                         blocks 512..767 -> U_h rows (dec @ U_a).
// ---------------------------------------------------------------------------
__global__ void proj_kernel(const float* __restrict__ enc,
                            const float* __restrict__ dec,
                            const float* __restrict__ Wa,
                            const float* __restrict__ Ua)
{
    __shared__ float xs[8][128];
    const int bid = blockIdx.x;
    const int t   = threadIdx.x;

    const float* x;
    const float* M;
    float*       out;
    int row0;
    if (bid < (B_ * TE_ / 8)) {
        row0 = bid * 8;
        x = enc;  M = Wa;  out = g_Ws;
    } else {
        row0 = (bid - (B_ * TE_ / 8)) * 8;
        x = dec;  M = Ua;  out = g_Uh;
    }

#pragma unroll
    for (int r = 0; r < 8; ++r)
        xs[r][t] = x[(size_t)(row0 + r) * H_ + t];
    __syncthreads();

    float acc[8];
#pragma unroll
    for (int r = 0; r < 8; ++r) acc[r] = 0.f;

#pragma unroll 4
    for (int h = 0; h < H_; ++h) {
        const float w = M[h * H_ + t];
#pragma unroll
        for (int r = 0; r < 8; ++r)
            acc[r] = fmaf(xs[r][h], w, acc[r]);
    }

#pragma unroll
    for (int r = 0; r < 8; ++r)
        out[(size_t)(row0 + r) * H_ + t] = acc[r];
}

// ---------------------------------------------------------------------------
// Block-wide reduction (256 threads, 8 warps)
// ---------------------------------------------------------------------------
__device__ __forceinline__ float block_reduce8(float v, bool is_max, float* red)
{
#pragma unroll
    for (int o = 16; o > 0; o >>= 1) {
        float other = __shfl_xor_sync(0xffffffffu, v, o);
        v = is_max ? fmaxf(v, other) : (v + other);
    }
    const int warp = threadIdx.x >> 5;
    if ((threadIdx.x & 31) == 0) red[warp] = v;
    __syncthreads();
    float r;
    if (is_max) {
        r = fmaxf(fmaxf(fmaxf(red[0], red[1]), fmaxf(red[2], red[3])),
                  fmaxf(fmaxf(red[4], red[5]), fmaxf(red[6], red[7])));
    } else {
        r = ((red[0] + red[1]) + (red[2] + red[3])) +
            ((red[4] + red[5]) + (red[6] + red[7]));
    }
    __syncthreads();
    return r;
}

// ---------------------------------------------------------------------------
// Kernel 2: fused energies + softmax + context.
// Grid: (TD_/DT_, B_).  Block: 256 threads (8 warps).
// Warp w: dd = w & 3 (decoder step), sub = w >> 2 (which 32-row half of tile).
// ---------------------------------------------------------------------------
__global__ __launch_bounds__(THREADS2)
void attn_kernel(const float* __restrict__ enc,
                 const float* __restrict__ Va,
                 float* __restrict__ c_out,  // [B,TD,H]
                 float* __restrict__ e_out)  // [B,TD,TE]
{
    extern __shared__ char smem_raw[];
    // layout: ws4 [TT_*33 float4] | uh4 [DT_*32 float4] | v4s [32 float4]
    //         | es [DT_*TE_ float] | red [8 float]
    float4* ws4 = (float4*)smem_raw;                                  // 33792 B
    float4* uh4 = (float4*)(smem_raw + TT_ * 33 * 16);                //  2048 B
    float4* v4s = (float4*)(smem_raw + TT_ * 33 * 16 + DT_ * 32 * 16);//   512 B
    float*  es  = (float*) (smem_raw + TT_ * 33 * 16 + DT_ * 32 * 16 + 512);
    float*  red = (float*) (smem_raw + TT_ * 33 * 16 + DT_ * 32 * 16 + 512
                            + DT_ * TE_ * 4);

    const int b    = blockIdx.y;
    const int d0   = blockIdx.x * DT_;
    const int tid  = threadIdx.x;
    const int lane = tid & 31;
    const int warp = tid >> 5;
    const int dd   = warp & 3;   // decoder step within block
    const int sub  = warp >> 2;  // 0/1: which 32-row half of the 64-row tile

    // stage U_h rows and V
    if (tid < DT_ * 32) {
        const float4* uh_src = (const float4*)(g_Uh + ((size_t)b * TD_ + d0) * H_);
        uh4[tid] = uh_src[tid];
    }
    if (tid >= 128 && tid < 160) v4s[tid - 128] = ((const float4*)Va)[tid - 128];

    // ----- Phase A: energies -----
    const int n_tiles = TE_ / TT_;   // 16
    for (int tile = 0; tile < n_tiles; ++tile) {
        __syncthreads();
        const float4* src = (const float4*)(g_Ws + ((size_t)b * TE_ + tile * TT_) * H_);
#pragma unroll
        for (int i = 0; i < (TT_ * 32) / THREADS2; ++i) {   // 8 iters
            int f = tid + i * THREADS2;
            int r = f >> 5, q = f & 31;
            ws4[r * 33 + q] = src[f];
        }
        __syncthreads();

        const int row = sub * 32 + lane;   // row within tile -> t index
        float acc = 0.f;
#pragma unroll 8
        for (int q = 0; q < 32; ++q) {
            const float4 wv = ws4[row * 33 + q];
            const float4 uv = uh4[dd * 32 + q];   // warp broadcast
            const float4 vv = v4s[q];             // warp broadcast
            acc = fmaf(vv.x, tanhfast(wv.x + uv.x), acc);
            acc = fmaf(vv.y, tanhfast(wv.y + uv.y), acc);
            acc = fmaf(vv.z, tanhfast(wv.z + uv.z), acc);
            acc = fmaf(vv.w, tanhfast(wv.w + uv.w), acc);
        }
        es[dd * TE_ + tile * TT_ + row] = acc;
    }
    __syncthreads();

    // ----- Phase B: softmax over TE per decoder step -----
    for (int d2 = 0; d2 < DT_; ++d2) {
        float m = -CUDART_INF_F;
        for (int i = tid; i < TE_; i += THREADS2)
            m = fmaxf(m, es[d2 * TE_ + i]);
        m = block_reduce8(m, true, red);

        float s = 0.f;
        for (int i = tid; i < TE_; i += THREADS2) {
            float ex = __expf(es[d2 * TE_ + i] - m);
            es[d2 * TE_ + i] = ex;
            s += ex;
        }
        s = block_reduce8(s, false, red);
        const float inv = 1.f / s;

        float* eo = e_out + ((size_t)b * TD_ + d0 + d2) * TE_;
        for (int i = tid; i < TE_; i += THREADS2) {
            float p = es[d2 * TE_ + i] * inv;
            es[d2 * TE_ + i] = p;
            eo[i] = p;
        }
        __syncthreads();
    }

    // ----- Phase C: context c[b,d,:] = sum_t e[t] * enc[b,t,:] -----
    // warp w: dd = w&3, rows sub*32..sub*32+31 of each tile; lane owns float4 hq.
    float4 acc4 = make_float4(0.f, 0.f, 0.f, 0.f);
    const int hq = lane;

    for (int tile = 0; tile < n_tiles; ++tile) {
        __syncthreads();
        const float4* src = (const float4*)(enc + ((size_t)b * TE_ + tile * TT_) * H_);
#pragma unroll
        for (int i = 0; i < (TT_ * 32) / THREADS2; ++i) {
            int f = tid + i * THREADS2;
            int r = f >> 5, q = f & 31;
            ws4[r * 33 + q] = src[f];
        }
        __syncthreads();

#pragma unroll 8
        for (int r = 0; r < 32; ++r) {
            const int row = sub * 32 + r;
            const float  w  = es[dd * TE_ + tile * TT_ + row];  // warp broadcast
            const float4 ev = ws4[row * 33 + hq];               // conflict-free
            acc4.x = fmaf(w, ev.x, acc4.x);
            acc4.y = fmaf(w, ev.y, acc4.y);
            acc4.z = fmaf(w, ev.z, acc4.z);
            acc4.w = fmaf(w, ev.w, acc4.w);
        }
    }

    // combine the two warps per dd through uh4 (dead after phase A)
    if (sub == 1) {
        uh4[dd * 32 + hq] = acc4;
    }
    __syncthreads();
    if (sub == 0) {
        const float4 o = uh4[dd * 32 + hq];
        acc4.x += o.x; acc4.y += o.y; acc4.z += o.z; acc4.w += o.w;
        float4* co = (float4*)(c_out + ((size_t)b * TD_ + d0 + dd) * H_);
        co[hq] = acc4;
    }
}

// ---------------------------------------------------------------------------
extern "C" void kernel_launch(void* const* d_in, const int* in_sizes, int n_in,
                              void* d_out, int out_size)
{
    const float* enc = (const float*)d_in[0];   // [B,TE,H]
    const float* dec = (const float*)d_in[1];   // [B,TD,H]
    const float* Wa  = (const float*)d_in[2];   // [H,H]
    const float* Ua  = (const float*)d_in[3];   // [H,H]
    const float* Va  = (const float*)d_in[4];   // [H,1]

    float* c_out = (float*)d_out;                       // [B,TD,H]
    float* e_out = c_out + (size_t)B_ * TD_ * H_;       // [B,TD,TE]

    const int smem_bytes = TT_ * 33 * 16      // ws4
                         + DT_ * 32 * 16      // uh4
                         + 512                // v4s
                         + DT_ * TE_ * 4      // es
                         + 8 * 4;             // red
    static bool attr_set = false;
    if (!attr_set) {
        cudaFuncSetAttribute(attn_kernel,
                             cudaFuncAttributeMaxDynamicSharedMemorySize,
                             smem_bytes);
        attr_set = true;
    }

    proj_kernel<<<(B_ * TE_ / 8) + (B_ * TD_ / 8), 128>>>(enc, dec, Wa, Ua);

    dim3 grid(TD_ / DT_, B_);
    attn_kernel<<<grid, THREADS2, smem_bytes>>>(enc, Va, c_out, e_out);
}

// round 4
// speedup vs baseline: 1.5052x; 1.3865x over previous
#include <cuda_runtime.h>
#include <cuda_bf16.h>
#include <math_constants.h>

// Problem constants
#define B_  4
#define TE_ 1024
#define TD_ 512
#define H_  128

#define DT_ 4        // decoder steps per block
#define TT_ 64       // encoder-t tile rows staged in smem (phase A)
#define THREADS2 256 // 8 warps

// Scratch for projections
__device__ float g_Ws[B_ * TE_ * H_]; // [B,TE,H]
__device__ float g_Uh[B_ * TD_ * H_]; // [B,TD,H]

__device__ __forceinline__ float tanhfast(float x) {
    float y;
    asm("tanh.approx.f32 %0, %1;" : "=f"(y) : "f"(x));
    return y;
}

// ---------------------------------------------------------------------------
// Kernel 1: projections (enc @ W_a -> g_Ws, dec @ U_a -> g_Uh)
// ---------------------------------------------------------------------------
__global__ void proj_kernel(const float* __restrict__ enc,
                            const float* __restrict__ dec,
                            const float* __restrict__ Wa,
                            const float* __restrict__ Ua)
{
    __shared__ float xs[8][128];
    const int bid = blockIdx.x;
    const int t   = threadIdx.x;

    const float* x;
    const float* M;
    float*       out;
    int row0;
    if (bid < (B_ * TE_ / 8)) {
        row0 = bid * 8;
        x = enc;  M = Wa;  out = g_Ws;
    } else {
        row0 = (bid - (B_ * TE_ / 8)) * 8;
        x = dec;  M = Ua;  out = g_Uh;
    }

#pragma unroll
    for (int r = 0; r < 8; ++r)
        xs[r][t] = x[(size_t)(row0 + r) * H_ + t];
    __syncthreads();

    float acc[8];
#pragma unroll
    for (int r = 0; r < 8; ++r) acc[r] = 0.f;

#pragma unroll 4
    for (int h = 0; h < H_; ++h) {
        const float w = M[h * H_ + t];
#pragma unroll
        for (int r = 0; r < 8; ++r)
            acc[r] = fmaf(xs[r][h], w, acc[r]);
    }

#pragma unroll
    for (int r = 0; r < 8; ++r)
        out[(size_t)(row0 + r) * H_ + t] = acc[r];
}

// ---------------------------------------------------------------------------
// Block reduction (256 threads, 8 warps)
// ---------------------------------------------------------------------------
__device__ __forceinline__ float block_reduce8(float v, bool is_max, float* red)
{
#pragma unroll
    for (int o = 16; o > 0; o >>= 1) {
        float other = __shfl_xor_sync(0xffffffffu, v, o);
        v = is_max ? fmaxf(v, other) : (v + other);
    }
    const int warp = threadIdx.x >> 5;
    if ((threadIdx.x & 31) == 0) red[warp] = v;
    __syncthreads();
    float r;
    if (is_max) {
        r = fmaxf(fmaxf(fmaxf(red[0], red[1]), fmaxf(red[2], red[3])),
                  fmaxf(fmaxf(red[4], red[5]), fmaxf(red[6], red[7])));
    } else {
        r = ((red[0] + red[1]) + (red[2] + red[3])) +
            ((red[4] + red[5]) + (red[6] + red[7]));
    }
    __syncthreads();
    return r;
}

// ---------------------------------------------------------------------------
// Kernel 2: fused energies + softmax + context.
// Grid (TD_/DT_, B_), 256 threads.
// Phase A: warp w -> sub = w&1 (row half), g = w>>1 (h-quarter).
//          Thread handles 1 encoder row x 4 decoder steps x 32 h-vals.
// Phase C: warp w -> rows w*8.. step 64; lane = float4 column of H.
//          Thread accumulates 4 dd simultaneously; enc read direct from GMEM.
// ---------------------------------------------------------------------------
__global__ __launch_bounds__(THREADS2)
void attn_kernel(const float* __restrict__ enc,
                 const float* __restrict__ Va,
                 float* __restrict__ c_out,  // [B,TD,H]
                 float* __restrict__ e_out)  // [B,TD,TE]
{
    extern __shared__ char smem_raw[];
    float4* ws4   = (float4*)smem_raw;                          // TT_*33*16 = 33792 B
    float4* uh4   = (float4*)(smem_raw + 33792);                // 2048 B
    float4* v4s   = (float4*)(smem_raw + 33792 + 2048);         // 512 B
    float*  es_t  = (float*) (smem_raw + 33792 + 2048 + 512);   // [TE_][4] = 16384 B
    float*  esp   = (float*) (smem_raw + 33792 + 2048 + 512 + 16384); // [4][64][4] = 4096 B
    float*  red   = (float*) (smem_raw + 33792 + 2048 + 512 + 16384 + 4096); // 32 B

    const int b    = blockIdx.y;
    const int d0   = blockIdx.x * DT_;
    const int tid  = threadIdx.x;
    const int lane = tid & 31;
    const int warp = tid >> 5;

    // stage U_h rows (4 x 128 floats) and V (128 floats)
    if (tid < DT_ * 32) {
        const float4* uh_src = (const float4*)(g_Uh + ((size_t)b * TD_ + d0) * H_);
        uh4[tid] = uh_src[tid];
    }
    if (tid >= 128 && tid < 160) v4s[tid - 128] = ((const float4*)Va)[tid - 128];

    // ----- Phase A: energies, thread = (row, 4 dd), warp group splits h -----
    const int sub = warp & 1;        // which 32-row half of the 64-row tile
    const int g   = warp >> 1;       // h-quarter: q in [g*8, g*8+8)
    const int row = sub * 32 + lane;

    const int n_tiles = TE_ / TT_;   // 16
    for (int tile = 0; tile < n_tiles; ++tile) {
        __syncthreads();
        // stage Ws tile (64 rows x 128 floats), float4 padded-33 layout
        const float4* src = (const float4*)(g_Ws + ((size_t)b * TE_ + tile * TT_) * H_);
#pragma unroll
        for (int i = 0; i < (TT_ * 32) / THREADS2; ++i) {   // 8
            int f = tid + i * THREADS2;
            int r = f >> 5, q = f & 31;
            ws4[r * 33 + q] = src[f];
        }
        __syncthreads();

        float a0 = 0.f, a1 = 0.f, a2 = 0.f, a3 = 0.f;
#pragma unroll 4
        for (int qq = 0; qq < 8; ++qq) {
            const int q = g * 8 + qq;
            const float4 wv = ws4[row * 33 + q];
            const float4 vv = v4s[q];                 // broadcast
            const float4 u0 = uh4[q];                 // broadcast
            const float4 u1 = uh4[32 + q];
            const float4 u2 = uh4[64 + q];
            const float4 u3 = uh4[96 + q];
            a0 = fmaf(vv.x, tanhfast(wv.x + u0.x), a0);
            a0 = fmaf(vv.y, tanhfast(wv.y + u0.y), a0);
            a0 = fmaf(vv.z, tanhfast(wv.z + u0.z), a0);
            a0 = fmaf(vv.w, tanhfast(wv.w + u0.w), a0);
            a1 = fmaf(vv.x, tanhfast(wv.x + u1.x), a1);
            a1 = fmaf(vv.y, tanhfast(wv.y + u1.y), a1);
            a1 = fmaf(vv.z, tanhfast(wv.z + u1.z), a1);
            a1 = fmaf(vv.w, tanhfast(wv.w + u1.w), a1);
            a2 = fmaf(vv.x, tanhfast(wv.x + u2.x), a2);
            a2 = fmaf(vv.y, tanhfast(wv.y + u2.y), a2);
            a2 = fmaf(vv.z, tanhfast(wv.z + u2.z), a2);
            a2 = fmaf(vv.w, tanhfast(wv.w + u2.w), a2);
            a3 = fmaf(vv.x, tanhfast(wv.x + u3.x), a3);
            a3 = fmaf(vv.y, tanhfast(wv.y + u3.y), a3);
            a3 = fmaf(vv.z, tanhfast(wv.z + u3.z), a3);
            a3 = fmaf(vv.w, tanhfast(wv.w + u3.w), a3);
        }
        // store partials: esp[g][row][0..3] (contiguous float4, conflict-free)
        ((float4*)esp)[g * 64 + row] = make_float4(a0, a1, a2, a3);
        __syncthreads();

        // reduce 4 h-quarter partials -> es_t[tile*64+row][dd]
        {
            // tid -> (row2 = tid>>2, dd = tid&3); read esp[g*256 + tid]
            float s = esp[tid] + esp[256 + tid] + esp[512 + tid] + esp[768 + tid];
            es_t[tile * 256 + tid] = s;
        }
    }
    __syncthreads();

    // ----- Phase B: softmax over TE per decoder step (es_t layout [t][dd]) -----
    for (int dd = 0; dd < DT_; ++dd) {
        float m = -CUDART_INF_F;
        for (int i = tid; i < TE_; i += THREADS2)
            m = fmaxf(m, es_t[i * 4 + dd]);
        m = block_reduce8(m, true, red);

        float s = 0.f;
        for (int i = tid; i < TE_; i += THREADS2) {
            float ex = __expf(es_t[i * 4 + dd] - m);
            es_t[i * 4 + dd] = ex;
            s += ex;
        }
        s = block_reduce8(s, false, red);
        const float inv = 1.f / s;

        float* eo = e_out + ((size_t)b * TD_ + d0 + dd) * TE_;
        for (int i = tid; i < TE_; i += THREADS2) {
            float p = es_t[i * 4 + dd] * inv;
            es_t[i * 4 + dd] = p;
            eo[i] = p;
        }
        __syncthreads();
    }

    // ----- Phase C: context, thread accumulates 4 dd x float4(H) -----
    float4 c0 = make_float4(0.f,0.f,0.f,0.f);
    float4 c1 = make_float4(0.f,0.f,0.f,0.f);
    float4 c2 = make_float4(0.f,0.f,0.f,0.f);
    float4 c3 = make_float4(0.f,0.f,0.f,0.f);

    const float4* encb = (const float4*)(enc + (size_t)b * TE_ * H_);
    for (int t0 = warp * 8; t0 < TE_; t0 += 64) {
#pragma unroll
        for (int r = 0; r < 8; ++r) {
            const int t = t0 + r;
            const float4 ev = encb[(size_t)t * 32 + lane];   // coalesced LDG.128
            const float4 e4 = ((const float4*)es_t)[t];      // broadcast: 4 dd weights
            c0.x = fmaf(e4.x, ev.x, c0.x); c0.y = fmaf(e4.x, ev.y, c0.y);
            c0.z = fmaf(e4.x, ev.z, c0.z); c0.w = fmaf(e4.x, ev.w, c0.w);
            c1.x = fmaf(e4.y, ev.x, c1.x); c1.y = fmaf(e4.y, ev.y, c1.y);
            c1.z = fmaf(e4.y, ev.z, c1.z); c1.w = fmaf(e4.y, ev.w, c1.w);
            c2.x = fmaf(e4.z, ev.x, c2.x); c2.y = fmaf(e4.z, ev.y, c2.y);
            c2.z = fmaf(e4.z, ev.z, c2.z); c2.w = fmaf(e4.z, ev.w, c2.w);
            c3.x = fmaf(e4.w, ev.x, c3.x); c3.y = fmaf(e4.w, ev.y, c3.y);
            c3.z = fmaf(e4.w, ev.z, c3.z); c3.w = fmaf(e4.w, ev.w, c3.w);
        }
    }

    // cross-warp reduction through ws4 (dead since phase A): cp[w][dd][lane]
    __syncthreads();
    float4* cp = ws4;   // needs 8*4*32 float4 = 16 KB (fits in 33.8 KB)
    cp[(warp * 4 + 0) * 32 + lane] = c0;
    cp[(warp * 4 + 1) * 32 + lane] = c1;
    cp[(warp * 4 + 2) * 32 + lane] = c2;
    cp[(warp * 4 + 3) * 32 + lane] = c3;
    __syncthreads();

    if (tid < 128) {
        const int dd = tid >> 5;     // 0..3
        const int hq = tid & 31;     // float4 column
        float4 s = make_float4(0.f,0.f,0.f,0.f);
#pragma unroll
        for (int w = 0; w < 8; ++w) {
            const float4 p = cp[(w * 4 + dd) * 32 + hq];
            s.x += p.x; s.y += p.y; s.z += p.z; s.w += p.w;
        }
        float4* co = (float4*)(c_out + ((size_t)b * TD_ + d0 + dd) * H_);
        co[hq] = s;
    }
}

// ---------------------------------------------------------------------------
extern "C" void kernel_launch(void* const* d_in, const int* in_sizes, int n_in,
                              void* d_out, int out_size)
{
    const float* enc = (const float*)d_in[0];   // [B,TE,H]
    const float* dec = (const float*)d_in[1];   // [B,TD,H]
    const float* Wa  = (const float*)d_in[2];   // [H,H]
    const float* Ua  = (const float*)d_in[3];   // [H,H]
    const float* Va  = (const float*)d_in[4];   // [H,1]

    float* c_out = (float*)d_out;                       // [B,TD,H]
    float* e_out = c_out + (size_t)B_ * TD_ * H_;       // [B,TD,TE]

    const int smem_bytes = 33792 + 2048 + 512 + 16384 + 4096 + 32;
    cudaFuncSetAttribute(attn_kernel,
                         cudaFuncAttributeMaxDynamicSharedMemorySize,
                         smem_bytes);

    proj_kernel<<<(B_ * TE_ / 8) + (B_ * TD_ / 8), 128>>>(enc, dec, Wa, Ua);

    dim3 grid(TD_ / DT_, B_);
    attn_kernel<<<grid, THREADS2, smem_bytes>>>(enc, Va, c_out, e_out);
}

// round 7
// speedup vs baseline: 1.5277x; 1.0150x over previous
#include <cuda_runtime.h>
#include <cuda_bf16.h>
#include <math_constants.h>

// Problem constants
#define B_  4
#define TE_ 1024
#define TD_ 512
#define H_  128

#define DT_ 4        // decoder steps per block
#define THREADS2 256 // 8 warps

// Scratch: transposed encoder projection wsT[b][q][t][c]  (q = h/4 group, c = h%4)
__device__ float g_WsT[B_ * TE_ * H_];
__device__ float g_Uh [B_ * TD_ * H_]; // [B,TD,H]

__device__ __forceinline__ float tanhfast(float x) {
    float y;
    asm("tanh.approx.f32 %0, %1;" : "=f"(y) : "f"(x));
    return y;
}

// ---------------------------------------------------------------------------
// Kernel 1: projections.  enc @ W_a -> g_WsT (transposed), dec @ U_a -> g_Uh.
// ---------------------------------------------------------------------------
__global__ void proj_kernel(const float* __restrict__ enc,
                            const float* __restrict__ dec,
                            const float* __restrict__ Wa,
                            const float* __restrict__ Ua)
{
    __shared__ float xs[8][128];
    const int bid = blockIdx.x;
    const int t   = threadIdx.x;

    const bool is_ws = (bid < (B_ * TE_ / 8));
    const float* x = is_ws ? enc : dec;
    const float* M = is_ws ? Wa  : Ua;
    const int row0 = is_ws ? bid * 8 : (bid - (B_ * TE_ / 8)) * 8;

#pragma unroll
    for (int r = 0; r < 8; ++r)
        xs[r][t] = x[(size_t)(row0 + r) * H_ + t];
    __syncthreads();

    float acc[8];
#pragma unroll
    for (int r = 0; r < 8; ++r) acc[r] = 0.f;

#pragma unroll 4
    for (int h = 0; h < H_; ++h) {
        const float w = M[h * H_ + t];
#pragma unroll
        for (int r = 0; r < 8; ++r)
            acc[r] = fmaf(xs[r][h], w, acc[r]);
    }

    if (is_ws) {
        // transposed store: wsT[b][q][tt][c],  q = t>>2, c = t&3
        const int q = t >> 2, c = t & 3;
#pragma unroll
        for (int r = 0; r < 8; ++r) {
            const int grow = row0 + r;            // global enc row in [0, B*TE)
            const int bb = grow >> 10;            // / TE_
            const int tt = grow & (TE_ - 1);
            g_WsT[((size_t)(bb * 32 + q) * TE_ + tt) * 4 + c] = acc[r];
        }
    } else {
#pragma unroll
        for (int r = 0; r < 8; ++r)
            g_Uh[(size_t)(row0 + r) * H_ + t] = acc[r];
    }
}

// ---------------------------------------------------------------------------
// Block reduction (256 threads, 8 warps)
// ---------------------------------------------------------------------------
__device__ __forceinline__ float block_reduce8(float v, bool is_max, float* red)
{
#pragma unroll
    for (int o = 16; o > 0; o >>= 1) {
        float other = __shfl_xor_sync(0xffffffffu, v, o);
        v = is_max ? fmaxf(v, other) : (v + other);
    }
    const int warp = threadIdx.x >> 5;
    if ((threadIdx.x & 31) == 0) red[warp] = v;
    __syncthreads();
    float r;
    if (is_max) {
        r = fmaxf(fmaxf(fmaxf(red[0], red[1]), fmaxf(red[2], red[3])),
                  fmaxf(fmaxf(red[4], red[5]), fmaxf(red[6], red[7])));
    } else {
        r = ((red[0] + red[1]) + (red[2] + red[3])) +
            ((red[4] + red[5]) + (red[6] + red[7]));
    }
    __syncthreads();
    return r;
}

// ---------------------------------------------------------------------------
// Kernel 2: fused energies + softmax + context.  Grid (TD_/DT_, B_), 256 thr.
// Phase A (no barriers): warp w -> g = w&1 (h-half, 16 q-groups),
//   half = w>>1 (t-chunks ch ≡ half mod 4).  Reads wsT coalesced from GMEM,
//   writes private partial plane ep[g][dd][t].
// ---------------------------------------------------------------------------
__global__ __launch_bounds__(THREADS2)
void attn_kernel(const float* __restrict__ enc,
                 const float* __restrict__ Va,
                 float* __restrict__ c_out,  // [B,TD,H]
                 float* __restrict__ e_out)  // [B,TD,TE]
{
    extern __shared__ char smem_raw[];
    float4* uh4 = (float4*)smem_raw;                         // 128 f4 = 2048 B
    float4* v4s = (float4*)(smem_raw + 2048);                //  32 f4 =  512 B
    float*  ep  = (float*) (smem_raw + 2560);                // [2][4][1024] = 32768 B
    float*  esf = (float*) (smem_raw + 2560 + 32768);        // [1024][4]   = 16384 B
    float*  red = (float*) (smem_raw + 2560 + 32768 + 16384);// 32 B

    const int b    = blockIdx.y;
    const int d0   = blockIdx.x * DT_;
    const int tid  = threadIdx.x;
    const int lane = tid & 31;
    const int warp = tid >> 5;

    // stage U_h (4 rows x 128) and V (128)
    if (tid < DT_ * 32) {
        const float4* uh_src = (const float4*)(g_Uh + ((size_t)b * TD_ + d0) * H_);
        uh4[tid] = uh_src[tid];
    }
    if (tid >= 128 && tid < 160) v4s[tid - 128] = ((const float4*)Va)[tid - 128];
    __syncthreads();

    // ----- Phase A: energies, barrier-free -----
    {
        const int g    = warp & 1;     // h-half: q in [g*16, g*16+16)
        const int half = warp >> 1;    // t-chunk residue (mod 4)
        const float4* wsT4 = (const float4*)g_WsT + (size_t)b * 32 * TE_;
        float* epg = ep + g * (DT_ * TE_);

        for (int ch = half; ch < TE_ / 32; ch += 4) {
            const int t = ch * 32 + lane;
            float a0 = 0.f, a1 = 0.f, a2 = 0.f, a3 = 0.f;
#pragma unroll 4
            for (int qq = 0; qq < 16; ++qq) {
                const int q = g * 16 + qq;
                const float4 wv = wsT4[(size_t)q * TE_ + t];  // coalesced LDG.128
                const float4 vv = v4s[q];                     // broadcast
                const float4 u0 = uh4[q];
                const float4 u1 = uh4[32 + q];
                const float4 u2 = uh4[64 + q];
                const float4 u3 = uh4[96 + q];
                a0 = fmaf(vv.x, tanhfast(wv.x + u0.x), a0);
                a0 = fmaf(vv.y, tanhfast(wv.y + u0.y), a0);
                a0 = fmaf(vv.z, tanhfast(wv.z + u0.z), a0);
                a0 = fmaf(vv.w, tanhfast(wv.w + u0.w), a0);
                a1 = fmaf(vv.x, tanhfast(wv.x + u1.x), a1);
                a1 = fmaf(vv.y, tanhfast(wv.y + u1.y), a1);
                a1 = fmaf(vv.z, tanhfast(wv.z + u1.z), a1);
                a1 = fmaf(vv.w, tanhfast(wv.w + u1.w), a1);
                a2 = fmaf(vv.x, tanhfast(wv.x + u2.x), a2);
                a2 = fmaf(vv.y, tanhfast(wv.y + u2.y), a2);
                a2 = fmaf(vv.z, tanhfast(wv.z + u2.z), a2);
                a2 = fmaf(vv.w, tanhfast(wv.w + u2.w), a2);
                a3 = fmaf(vv.x, tanhfast(wv.x + u3.x), a3);
                a3 = fmaf(vv.y, tanhfast(wv.y + u3.y), a3);
                a3 = fmaf(vv.z, tanhfast(wv.z + u3.z), a3);
                a3 = fmaf(vv.w, tanhfast(wv.w + u3.w), a3);
            }
            // private plane, conflict-free, no race
            epg[0 * TE_ + t] = a0;
            epg[1 * TE_ + t] = a1;
            epg[2 * TE_ + t] = a2;
            epg[3 * TE_ + t] = a3;
        }
    }
    __syncthreads();

    // ----- Phase B: fold h-halves + softmax per decoder step -----
    for (int dd = 0; dd < DT_; ++dd) {
        float* p0 = ep + dd * TE_;
        float* p1 = ep + DT_ * TE_ + dd * TE_;

        float m = -CUDART_INF_F;
        for (int i = tid; i < TE_; i += THREADS2) {
            float s = p0[i] + p1[i];
            p0[i] = s;
            m = fmaxf(m, s);
        }
        m = block_reduce8(m, true, red);

        float s = 0.f;
        for (int i = tid; i < TE_; i += THREADS2) {
            float ex = __expf(p0[i] - m);
            p0[i] = ex;
            s += ex;
        }
        s = block_reduce8(s, false, red);
        const float inv = 1.f / s;

        float* eo = e_out + ((size_t)b * TD_ + d0 + dd) * TE_;
        for (int i = tid; i < TE_; i += THREADS2) {
            float p = p0[i] * inv;
            esf[i * 4 + dd] = p;    // [t][dd] for phase C
            eo[i] = p;
        }
        __syncthreads();
    }

    // ----- Phase C: context, thread accumulates 4 dd x float4(H) -----
    float4 c0 = make_float4(0.f,0.f,0.f,0.f);
    float4 c1 = make_float4(0.f,0.f,0.f,0.f);
    float4 c2 = make_float4(0.f,0.f,0.f,0.f);
    float4 c3 = make_float4(0.f,0.f,0.f,0.f);

    const float4* encb = (const float4*)(enc + (size_t)b * TE_ * H_);
    const float4* es4  = (const float4*)esf;
    for (int t0 = warp * 8; t0 < TE_; t0 += 64) {
#pragma unroll
        for (int r = 0; r < 8; ++r) {
            const int t = t0 + r;
            const float4 ev = encb[(size_t)t * 32 + lane];   // coalesced LDG.128
            const float4 e4 = es4[t];                        // broadcast
            c0.x = fmaf(e4.x, ev.x, c0.x); c0.y = fmaf(e4.x, ev.y, c0.y);
            c0.z = fmaf(e4.x, ev.z, c0.z); c0.w = fmaf(e4.x, ev.w, c0.w);
            c1.x = fmaf(e4.y, ev.x, c1.x); c1.y = fmaf(e4.y, ev.y, c1.y);
            c1.z = fmaf(e4.y, ev.z, c1.z); c1.w = fmaf(e4.y, ev.w, c1.w);
            c2.x = fmaf(e4.z, ev.x, c2.x); c2.y = fmaf(e4.z, ev.y, c2.y);
            c2.z = fmaf(e4.z, ev.z, c2.z); c2.w = fmaf(e4.z, ev.w, c2.w);
            c3.x = fmaf(e4.w, ev.x, c3.x); c3.y = fmaf(e4.w, ev.y, c3.y);
            c3.z = fmaf(e4.w, ev.z, c3.z); c3.w = fmaf(e4.w, ev.w, c3.w);
        }
    }

    // cross-warp reduce through ep[1] plane (dead after B): cp[w][dd][lane]
    __syncthreads();
    float4* cp = (float4*)(ep + DT_ * TE_);   // 16 KB
    cp[(warp * 4 + 0) * 32 + lane] = c0;
    cp[(warp * 4 + 1) * 32 + lane] = c1;
    cp[(warp * 4 + 2) * 32 + lane] = c2;
    cp[(warp * 4 + 3) * 32 + lane] = c3;
    __syncthreads();

    if (tid < 128) {
        const int dd = tid >> 5;
        const int hq = tid & 31;
        float4 s = make_float4(0.f,0.f,0.f,0.f);
#pragma unroll
        for (int w = 0; w < 8; ++w) {
            const float4 p = cp[(w * 4 + dd) * 32 + hq];
            s.x += p.x; s.y += p.y; s.z += p.z; s.w += p.w;
        }
        float4* co = (float4*)(c_out + ((size_t)b * TD_ + d0 + dd) * H_);
        co[hq] = s;
    }
}

// ---------------------------------------------------------------------------
extern "C" void kernel_launch(void* const* d_in, const int* in_sizes, int n_in,
                              void* d_out, int out_size)
{
    const float* enc = (const float*)d_in[0];   // [B,TE,H]
    const float* dec = (const float*)d_in[1];   // [B,TD,H]
    const float* Wa  = (const float*)d_in[2];   // [H,H]
    const float* Ua  = (const float*)d_in[3];   // [H,H]
    const float* Va  = (const float*)d_in[4];   // [H,1]

    float* c_out = (float*)d_out;                       // [B,TD,H]
    float* e_out = c_out + (size_t)B_ * TD_ * H_;       // [B,TD,TE]

    const int smem_bytes = 2048 + 512 + 32768 + 16384 + 32;
    cudaFuncSetAttribute(attn_kernel,
                         cudaFuncAttributeMaxDynamicSharedMemorySize,
                         smem_bytes);

    proj_kernel<<<(B_ * TE_ / 8) + (B_ * TD_ / 8), 128>>>(enc, dec, Wa, Ua);

    dim3 grid(TD_ / DT_, B_);
    attn_kernel<<<grid, THREADS2, smem_bytes>>>(enc, Va, c_out, e_out);
}

// round 10
// speedup vs baseline: 1.8011x; 1.1790x over previous
#include <cuda_runtime.h>
#include <cuda_bf16.h>
#include <math_constants.h>

// Problem constants
#define B_  4
#define TE_ 1024
#define TD_ 512
#define H_  128

#define DT_ 4        // decoder steps per block
#define THREADS2 256 // 8 warps

// Scratch: transposed encoder projection wsT[b][q][t][c]  (q = h/4 group, c = h%4)
__device__ float g_WsT[B_ * TE_ * H_];
__device__ float g_Uh [B_ * TD_ * H_]; // [B,TD,H]

__device__ __forceinline__ float tanhfast(float x) {
    float y;
    asm("tanh.approx.f32 %0, %1;" : "=f"(y) : "f"(x));
    return y;
}

// ---------------------------------------------------------------------------
// Kernel 1: projections.  enc @ W_a -> g_WsT (transposed), dec @ U_a -> g_Uh.
// ---------------------------------------------------------------------------
__global__ void proj_kernel(const float* __restrict__ enc,
                            const float* __restrict__ dec,
                            const float* __restrict__ Wa,
                            const float* __restrict__ Ua)
{
    __shared__ float xs[8][128];
    const int bid = blockIdx.x;
    const int t   = threadIdx.x;

    const bool is_ws = (bid < (B_ * TE_ / 8));
    const float* x = is_ws ? enc : dec;
    const float* M = is_ws ? Wa  : Ua;
    const int row0 = is_ws ? bid * 8 : (bid - (B_ * TE_ / 8)) * 8;

#pragma unroll
    for (int r = 0; r < 8; ++r)
        xs[r][t] = x[(size_t)(row0 + r) * H_ + t];
    __syncthreads();

    float acc[8];
#pragma unroll
    for (int r = 0; r < 8; ++r) acc[r] = 0.f;

#pragma unroll 4
    for (int h = 0; h < H_; ++h) {
        const float w = M[h * H_ + t];
#pragma unroll
        for (int r = 0; r < 8; ++r)
            acc[r] = fmaf(xs[r][h], w, acc[r]);
    }

    if (is_ws) {
        const int q = t >> 2, c = t & 3;
#pragma unroll
        for (int r = 0; r < 8; ++r) {
            const int grow = row0 + r;
            const int bb = grow >> 10;
            const int tt = grow & (TE_ - 1);
            g_WsT[((size_t)(bb * 32 + q) * TE_ + tt) * 4 + c] = acc[r];
        }
    } else {
#pragma unroll
        for (int r = 0; r < 8; ++r)
            g_Uh[(size_t)(row0 + r) * H_ + t] = acc[r];
    }
}

// ---------------------------------------------------------------------------
// Kernel 2: fused energies + shift-free softmax + context.
// Grid (TD_/DT_, B_), 256 threads (8 warps).
// Phase A: warp w owns t-chunks {w, w+8, w+16, w+24} (4 chunks of 32 t).
//   Outer loop over q keeps vv/u0..u3 in registers; inner loop over chunks.
//   Energies -> exp directly (bounded by sum|V| ~ 5, no overflow), private
//   esf[t][dd] stores + per-dd running sums.  No barriers in the hot loop.
// ---------------------------------------------------------------------------
__global__ __launch_bounds__(THREADS2, 3)
void attn_kernel(const float* __restrict__ enc,
                 const float* __restrict__ Va,
                 float* __restrict__ c_out,  // [B,TD,H]
                 float* __restrict__ e_out)  // [B,TD,TE]
{
    extern __shared__ char smem_raw[];
    float4* uh4   = (float4*)smem_raw;                       // 128 f4 = 2048 B
    float4* v4s   = (float4*)(smem_raw + 2048);              //  32 f4 =  512 B
    float*  esf   = (float*) (smem_raw + 2560);              // [1024][4] = 16384 B
    float4* cp    = (float4*)(smem_raw + 2560 + 16384);      // [8][4][32] = 16384 B
    float*  redsm = (float*) (smem_raw + 2560 + 32768);      // [8][4] = 128 B
    float*  invs  = (float*) (smem_raw + 2560 + 32768 + 128);// [4]

    const int b    = blockIdx.y;
    const int d0   = blockIdx.x * DT_;
    const int tid  = threadIdx.x;
    const int lane = tid & 31;
    const int warp = tid >> 5;

    // stage U_h (4 rows x 128) and V (128)
    if (tid < DT_ * 32) {
        const float4* uh_src = (const float4*)(g_Uh + ((size_t)b * TD_ + d0) * H_);
        uh4[tid] = uh_src[tid];
    }
    if (tid >= 128 && tid < 160) v4s[tid - 128] = ((const float4*)Va)[tid - 128];
    __syncthreads();

    // ----- Phase A: energies (q outer, chunks inner, regs for u/v) -----
    float acc[4][4];
#pragma unroll
    for (int c2 = 0; c2 < 4; ++c2)
#pragma unroll
        for (int dd = 0; dd < DT_; ++dd) acc[c2][dd] = 0.f;

    {
        const float4* wsT4 = (const float4*)g_WsT + (size_t)b * 32 * TE_;
#pragma unroll 1
        for (int q = 0; q < 32; ++q) {
            const float4 vv = v4s[q];
            const float4 u0 = uh4[q];
            const float4 u1 = uh4[32 + q];
            const float4 u2 = uh4[64 + q];
            const float4 u3 = uh4[96 + q];
            const float4* wrow = wsT4 + (size_t)q * TE_;
#pragma unroll
            for (int c2 = 0; c2 < 4; ++c2) {
                const int t = (warp + c2 * 8) * 32 + lane;
                const float4 wv = wrow[t];             // coalesced LDG.128 (L2)
                acc[c2][0] = fmaf(vv.x, tanhfast(wv.x + u0.x), acc[c2][0]);
                acc[c2][0] = fmaf(vv.y, tanhfast(wv.y + u0.y), acc[c2][0]);
                acc[c2][0] = fmaf(vv.z, tanhfast(wv.z + u0.z), acc[c2][0]);
                acc[c2][0] = fmaf(vv.w, tanhfast(wv.w + u0.w), acc[c2][0]);
                acc[c2][1] = fmaf(vv.x, tanhfast(wv.x + u1.x), acc[c2][1]);
                acc[c2][1] = fmaf(vv.y, tanhfast(wv.y + u1.y), acc[c2][1]);
                acc[c2][1] = fmaf(vv.z, tanhfast(wv.z + u1.z), acc[c2][1]);
                acc[c2][1] = fmaf(vv.w, tanhfast(wv.w + u1.w), acc[c2][1]);
                acc[c2][2] = fmaf(vv.x, tanhfast(wv.x + u2.x), acc[c2][2]);
                acc[c2][2] = fmaf(vv.y, tanhfast(wv.y + u2.y), acc[c2][2]);
                acc[c2][2] = fmaf(vv.z, tanhfast(wv.z + u2.z), acc[c2][2]);
                acc[c2][2] = fmaf(vv.w, tanhfast(wv.w + u2.w), acc[c2][2]);
                acc[c2][3] = fmaf(vv.x, tanhfast(wv.x + u3.x), acc[c2][3]);
                acc[c2][3] = fmaf(vv.y, tanhfast(wv.y + u3.y), acc[c2][3]);
                acc[c2][3] = fmaf(vv.z, tanhfast(wv.z + u3.z), acc[c2][3]);
                acc[c2][3] = fmaf(vv.w, tanhfast(wv.w + u3.w), acc[c2][3]);
            }
        }
    }

    // exp (shift-free: |e| <= sum|V| ~ 5.2, no overflow) + store + partial sums
    float s0 = 0.f, s1 = 0.f, s2 = 0.f, s3 = 0.f;
#pragma unroll
    for (int c2 = 0; c2 < 4; ++c2) {
        const int t = (warp + c2 * 8) * 32 + lane;
        const float e0 = __expf(acc[c2][0]);
        const float e1 = __expf(acc[c2][1]);
        const float e2 = __expf(acc[c2][2]);
        const float e3 = __expf(acc[c2][3]);
        ((float4*)esf)[t] = make_float4(e0, e1, e2, e3);
        s0 += e0; s1 += e1; s2 += e2; s3 += e3;
    }
#pragma unroll
    for (int o = 16; o > 0; o >>= 1) {
        s0 += __shfl_xor_sync(0xffffffffu, s0, o);
        s1 += __shfl_xor_sync(0xffffffffu, s1, o);
        s2 += __shfl_xor_sync(0xffffffffu, s2, o);
        s3 += __shfl_xor_sync(0xffffffffu, s3, o);
    }
    if (lane == 0) {
        redsm[warp * 4 + 0] = s0;
        redsm[warp * 4 + 1] = s1;
        redsm[warp * 4 + 2] = s2;
        redsm[warp * 4 + 3] = s3;
    }
    __syncthreads();
    if (tid < 4) {
        float s = 0.f;
#pragma unroll
        for (int w = 0; w < 8; ++w) s += redsm[w * 4 + tid];
        invs[tid] = 1.f / s;
    }
    __syncthreads();

    // ----- e_out write (normalized) -----
#pragma unroll
    for (int dd = 0; dd < DT_; ++dd) {
        const float inv = invs[dd];
        float* eo = e_out + ((size_t)b * TD_ + d0 + dd) * TE_;
        for (int i = tid; i < TE_; i += THREADS2)
            eo[i] = esf[i * 4 + dd] * inv;
    }

    // ----- Phase C: context with unnormalized weights -----
    float4 c0 = make_float4(0.f,0.f,0.f,0.f);
    float4 c1 = make_float4(0.f,0.f,0.f,0.f);
    float4 c2v = make_float4(0.f,0.f,0.f,0.f);
    float4 c3 = make_float4(0.f,0.f,0.f,0.f);

    const float4* encb = (const float4*)(enc + (size_t)b * TE_ * H_);
    const float4* es4  = (const float4*)esf;
    for (int t0 = warp * 8; t0 < TE_; t0 += 64) {
#pragma unroll
        for (int r = 0; r < 8; ++r) {
            const int t = t0 + r;
            const float4 ev = encb[(size_t)t * 32 + lane];   // coalesced LDG.128
            const float4 e4 = es4[t];                        // broadcast
            c0.x  = fmaf(e4.x, ev.x, c0.x);  c0.y  = fmaf(e4.x, ev.y, c0.y);
            c0.z  = fmaf(e4.x, ev.z, c0.z);  c0.w  = fmaf(e4.x, ev.w, c0.w);
            c1.x  = fmaf(e4.y, ev.x, c1.x);  c1.y  = fmaf(e4.y, ev.y, c1.y);
            c1.z  = fmaf(e4.y, ev.z, c1.z);  c1.w  = fmaf(e4.y, ev.w, c1.w);
            c2v.x = fmaf(e4.z, ev.x, c2v.x); c2v.y = fmaf(e4.z, ev.y, c2v.y);
            c2v.z = fmaf(e4.z, ev.z, c2v.z); c2v.w = fmaf(e4.z, ev.w, c2v.w);
            c3.x  = fmaf(e4.w, ev.x, c3.x);  c3.y  = fmaf(e4.w, ev.y, c3.y);
            c3.z  = fmaf(e4.w, ev.z, c3.z);  c3.w  = fmaf(e4.w, ev.w, c3.w);
        }
    }

    cp[(warp * 4 + 0) * 32 + lane] = c0;
    cp[(warp * 4 + 1) * 32 + lane] = c1;
    cp[(warp * 4 + 2) * 32 + lane] = c2v;
    cp[(warp * 4 + 3) * 32 + lane] = c3;
    __syncthreads();

    if (tid < 128) {
        const int dd = tid >> 5;
        const int hq = tid & 31;
        const float inv = invs[dd];
        float4 s = make_float4(0.f,0.f,0.f,0.f);
#pragma unroll
        for (int w = 0; w < 8; ++w) {
            const float4 p = cp[(w * 4 + dd) * 32 + hq];
            s.x += p.x; s.y += p.y; s.z += p.z; s.w += p.w;
        }
        s.x *= inv; s.y *= inv; s.z *= inv; s.w *= inv;
        float4* co = (float4*)(c_out + ((size_t)b * TD_ + d0 + dd) * H_);
        co[hq] = s;
    }
}

// ---------------------------------------------------------------------------
extern "C" void kernel_launch(void* const* d_in, const int* in_sizes, int n_in,
                              void* d_out, int out_size)
{
    const float* enc = (const float*)d_in[0];   // [B,TE,H]
    const float* dec = (const float*)d_in[1];   // [B,TD,H]
    const float* Wa  = (const float*)d_in[2];   // [H,H]
    const float* Ua  = (const float*)d_in[3];   // [H,H]
    const float* Va  = (const float*)d_in[4];   // [H,1]

    float* c_out = (float*)d_out;                       // [B,TD,H]
    float* e_out = c_out + (size_t)B_ * TD_ * H_;       // [B,TD,TE]

    const int smem_bytes = 2048 + 512 + 16384 + 16384 + 128 + 16;
    cudaFuncSetAttribute(attn_kernel,
                         cudaFuncAttributeMaxDynamicSharedMemorySize,
                         smem_bytes);

    proj_kernel<<<(B_ * TE_ / 8) + (B_ * TD_ / 8), 128>>>(enc, dec, Wa, Ua);

    dim3 grid(TD_ / DT_, B_);
    attn_kernel<<<grid, THREADS2, smem_bytes>>>(enc, Va, c_out, e_out);
}

// round 11
// speedup vs baseline: 1.8237x; 1.0126x over previous
#include <cuda_runtime.h>
#include <cuda_bf16.h>
#include <math_constants.h>

// Problem constants
#define B_  4
#define TE_ 1024
#define TD_ 512
#define H_  128

#define DT_ 4        // decoder steps per block
#define THREADS2 256 // 8 warps

// Scratch: transposed encoder projection wsT[b][q][t][c]  (q = h/4 group, c = h%4)
__device__ float g_WsT[B_ * TE_ * H_];
__device__ float g_Uh [B_ * TD_ * H_]; // [B,TD,H]

__device__ __forceinline__ float tanhfast(float x) {
    float y;
    asm("tanh.approx.f32 %0, %1;" : "=f"(y) : "f"(x));
    return y;
}

// ---------------------------------------------------------------------------
// Kernel 1: projections.  enc @ W_a -> g_WsT (transposed), dec @ U_a -> g_Uh.
// ---------------------------------------------------------------------------
__global__ void proj_kernel(const float* __restrict__ enc,
                            const float* __restrict__ dec,
                            const float* __restrict__ Wa,
                            const float* __restrict__ Ua)
{
    __shared__ float xs[8][128];
    const int bid = blockIdx.x;
    const int t   = threadIdx.x;

    const bool is_ws = (bid < (B_ * TE_ / 8));
    const float* x = is_ws ? enc : dec;
    const float* M = is_ws ? Wa  : Ua;
    const int row0 = is_ws ? bid * 8 : (bid - (B_ * TE_ / 8)) * 8;

#pragma unroll
    for (int r = 0; r < 8; ++r)
        xs[r][t] = x[(size_t)(row0 + r) * H_ + t];
    __syncthreads();

    float acc[8];
#pragma unroll
    for (int r = 0; r < 8; ++r) acc[r] = 0.f;

#pragma unroll 4
    for (int h = 0; h < H_; ++h) {
        const float w = M[h * H_ + t];
#pragma unroll
        for (int r = 0; r < 8; ++r)
            acc[r] = fmaf(xs[r][h], w, acc[r]);
    }

    if (is_ws) {
        const int q = t >> 2, c = t & 3;
#pragma unroll
        for (int r = 0; r < 8; ++r) {
            const int grow = row0 + r;
            const int bb = grow >> 10;
            const int tt = grow & (TE_ - 1);
            g_WsT[((size_t)(bb * 32 + q) * TE_ + tt) * 4 + c] = acc[r];
        }
    } else {
#pragma unroll
        for (int r = 0; r < 8; ++r)
            g_Uh[(size_t)(row0 + r) * H_ + t] = acc[r];
    }
}

// ---------------------------------------------------------------------------
// Kernel 2: fused energies + shift-free softmax + context.
// Grid (TD_/DT_, B_), 256 threads (8 warps), 4 blocks/SM -> single wave.
// ---------------------------------------------------------------------------
__global__ __launch_bounds__(THREADS2, 4)
void attn_kernel(const float* __restrict__ enc,
                 const float* __restrict__ Va,
                 float* __restrict__ c_out,  // [B,TD,H]
                 float* __restrict__ e_out)  // [B,TD,TE]
{
    extern __shared__ char smem_raw[];
    float4* uh4   = (float4*)smem_raw;                       // 128 f4 = 2048 B
    float4* v4s   = (float4*)(smem_raw + 2048);              //  32 f4 =  512 B
    float*  esf   = (float*) (smem_raw + 2560);              // [1024][4] = 16384 B
    float4* cp    = (float4*)(smem_raw + 2560 + 16384);      // [8][4][32] = 16384 B
    float*  redsm = (float*) (smem_raw + 2560 + 32768);      // [8][4] = 128 B
    float*  invs  = (float*) (smem_raw + 2560 + 32768 + 128);// [4]

    const int b    = blockIdx.y;
    const int d0   = blockIdx.x * DT_;
    const int tid  = threadIdx.x;
    const int lane = tid & 31;
    const int warp = tid >> 5;

    // stage U_h (4 rows x 128) and V (128)
    if (tid < DT_ * 32) {
        const float4* uh_src = (const float4*)(g_Uh + ((size_t)b * TD_ + d0) * H_);
        uh4[tid] = uh_src[tid];
    }
    if (tid >= 128 && tid < 160) v4s[tid - 128] = ((const float4*)Va)[tid - 128];
    __syncthreads();

    // ----- Phase A: energies (q outer, chunks inner, regs for u/v) -----
    float acc[4][4];
#pragma unroll
    for (int c2 = 0; c2 < 4; ++c2)
#pragma unroll
        for (int dd = 0; dd < DT_; ++dd) acc[c2][dd] = 0.f;

    {
        const float4* wsT4 = (const float4*)g_WsT + (size_t)b * 32 * TE_;
#pragma unroll 1
        for (int q = 0; q < 32; ++q) {
            const float4 vv = v4s[q];
            const float4 u0 = uh4[q];
            const float4 u1 = uh4[32 + q];
            const float4 u2 = uh4[64 + q];
            const float4 u3 = uh4[96 + q];
            const float4* wrow = wsT4 + (size_t)q * TE_;
#pragma unroll
            for (int c2 = 0; c2 < 4; ++c2) {
                const int t = (warp + c2 * 8) * 32 + lane;
                const float4 wv = wrow[t];             // coalesced LDG.128 (L2)
                acc[c2][0] = fmaf(vv.x, tanhfast(wv.x + u0.x), acc[c2][0]);
                acc[c2][0] = fmaf(vv.y, tanhfast(wv.y + u0.y), acc[c2][0]);
                acc[c2][0] = fmaf(vv.z, tanhfast(wv.z + u0.z), acc[c2][0]);
                acc[c2][0] = fmaf(vv.w, tanhfast(wv.w + u0.w), acc[c2][0]);
                acc[c2][1] = fmaf(vv.x, tanhfast(wv.x + u1.x), acc[c2][1]);
                acc[c2][1] = fmaf(vv.y, tanhfast(wv.y + u1.y), acc[c2][1]);
                acc[c2][1] = fmaf(vv.z, tanhfast(wv.z + u1.z), acc[c2][1]);
                acc[c2][1] = fmaf(vv.w, tanhfast(wv.w + u1.w), acc[c2][1]);
                acc[c2][2] = fmaf(vv.x, tanhfast(wv.x + u2.x), acc[c2][2]);
                acc[c2][2] = fmaf(vv.y, tanhfast(wv.y + u2.y), acc[c2][2]);
                acc[c2][2] = fmaf(vv.z, tanhfast(wv.z + u2.z), acc[c2][2]);
                acc[c2][2] = fmaf(vv.w, tanhfast(wv.w + u2.w), acc[c2][2]);
                acc[c2][3] = fmaf(vv.x, tanhfast(wv.x + u3.x), acc[c2][3]);
                acc[c2][3] = fmaf(vv.y, tanhfast(wv.y + u3.y), acc[c2][3]);
                acc[c2][3] = fmaf(vv.z, tanhfast(wv.z + u3.z), acc[c2][3]);
                acc[c2][3] = fmaf(vv.w, tanhfast(wv.w + u3.w), acc[c2][3]);
            }
        }
    }

    // exp (shift-free: |e| <= sum|V| ~ 5.2, no overflow) + store + partial sums
    float s0 = 0.f, s1 = 0.f, s2 = 0.f, s3 = 0.f;
#pragma unroll
    for (int c2 = 0; c2 < 4; ++c2) {
        const int t = (warp + c2 * 8) * 32 + lane;
        const float e0 = __expf(acc[c2][0]);
        const float e1 = __expf(acc[c2][1]);
        const float e2 = __expf(acc[c2][2]);
        const float e3 = __expf(acc[c2][3]);
        ((float4*)esf)[t] = make_float4(e0, e1, e2, e3);
        s0 += e0; s1 += e1; s2 += e2; s3 += e3;
    }
#pragma unroll
    for (int o = 16; o > 0; o >>= 1) {
        s0 += __shfl_xor_sync(0xffffffffu, s0, o);
        s1 += __shfl_xor_sync(0xffffffffu, s1, o);
        s2 += __shfl_xor_sync(0xffffffffu, s2, o);
        s3 += __shfl_xor_sync(0xffffffffu, s3, o);
    }
    if (lane == 0) {
        redsm[warp * 4 + 0] = s0;
        redsm[warp * 4 + 1] = s1;
        redsm[warp * 4 + 2] = s2;
        redsm[warp * 4 + 3] = s3;
    }
    __syncthreads();
    if (tid < 4) {
        float s = 0.f;
#pragma unroll
        for (int w = 0; w < 8; ++w) s += redsm[w * 4 + tid];
        invs[tid] = 1.f / s;
    }
    __syncthreads();

    // ----- e_out write: one conflict-free pass, thread owns one t -----
    {
        const float i0 = invs[0], i1 = invs[1], i2 = invs[2], i3 = invs[3];
        float* eo = e_out + ((size_t)b * TD_ + d0) * TE_;
#pragma unroll
        for (int c2 = 0; c2 < 4; ++c2) {
            const int t = c2 * THREADS2 + tid;
            const float4 e4 = ((const float4*)esf)[t];   // conflict-free LDS.128
            eo[t]            = e4.x * i0;
            eo[TE_ + t]      = e4.y * i1;
            eo[2 * TE_ + t]  = e4.z * i2;
            eo[3 * TE_ + t]  = e4.w * i3;
        }
    }

    // ----- Phase C: context with unnormalized weights -----
    float4 c0 = make_float4(0.f,0.f,0.f,0.f);
    float4 c1 = make_float4(0.f,0.f,0.f,0.f);
    float4 c2v = make_float4(0.f,0.f,0.f,0.f);
    float4 c3 = make_float4(0.f,0.f,0.f,0.f);

    const float4* encb = (const float4*)(enc + (size_t)b * TE_ * H_);
    const float4* es4  = (const float4*)esf;
    for (int t0 = warp * 8; t0 < TE_; t0 += 64) {
#pragma unroll
        for (int r = 0; r < 8; ++r) {
            const int t = t0 + r;
            const float4 ev = encb[(size_t)t * 32 + lane];   // coalesced LDG.128
            const float4 e4 = es4[t];                        // broadcast
            c0.x  = fmaf(e4.x, ev.x, c0.x);  c0.y  = fmaf(e4.x, ev.y, c0.y);
            c0.z  = fmaf(e4.x, ev.z, c0.z);  c0.w  = fmaf(e4.x, ev.w, c0.w);
            c1.x  = fmaf(e4.y, ev.x, c1.x);  c1.y  = fmaf(e4.y, ev.y, c1.y);
            c1.z  = fmaf(e4.y, ev.z, c1.z);  c1.w  = fmaf(e4.y, ev.w, c1.w);
            c2v.x = fmaf(e4.z, ev.x, c2v.x); c2v.y = fmaf(e4.z, ev.y, c2v.y);
            c2v.z = fmaf(e4.z, ev.z, c2v.z); c2v.w = fmaf(e4.z, ev.w, c2v.w);
            c3.x  = fmaf(e4.w, ev.x, c3.x);  c3.y  = fmaf(e4.w, ev.y, c3.y);
            c3.z  = fmaf(e4.w, ev.z, c3.z);  c3.w  = fmaf(e4.w, ev.w, c3.w);
        }
    }

    cp[(warp * 4 + 0) * 32 + lane] = c0;
    cp[(warp * 4 + 1) * 32 + lane] = c1;
    cp[(warp * 4 + 2) * 32 + lane] = c2v;
    cp[(warp * 4 + 3) * 32 + lane] = c3;
    __syncthreads();

    if (tid < 128) {
        const int dd = tid >> 5;
        const int hq = tid & 31;
        const float inv = invs[dd];
        float4 s = make_float4(0.f,0.f,0.f,0.f);
#pragma unroll
        for (int w = 0; w < 8; ++w) {
            const float4 p = cp[(w * 4 + dd) * 32 + hq];
            s.x += p.x; s.y += p.y; s.z += p.z; s.w += p.w;
        }
        s.x *= inv; s.y *= inv; s.z *= inv; s.w *= inv;
        float4* co = (float4*)(c_out + ((size_t)b * TD_ + d0 + dd) * H_);
        co[hq] = s;
    }
}

// ---------------------------------------------------------------------------
extern "C" void kernel_launch(void* const* d_in, const int* in_sizes, int n_in,
                              void* d_out, int out_size)
{
    const float* enc = (const float*)d_in[0];   // [B,TE,H]
    const float* dec = (const float*)d_in[1];   // [B,TD,H]
    const float* Wa  = (const float*)d_in[2];   // [H,H]
    const float* Ua  = (const float*)d_in[3];   // [H,H]
    const float* Va  = (const float*)d_in[4];   // [H,1]

    float* c_out = (float*)d_out;                       // [B,TD,H]
    float* e_out = c_out + (size_t)B_ * TD_ * H_;       // [B,TD,TE]

    const int smem_bytes = 2048 + 512 + 16384 + 16384 + 128 + 16;
    cudaFuncSetAttribute(attn_kernel,
                         cudaFuncAttributeMaxDynamicSharedMemorySize,
                         smem_bytes);

    proj_kernel<<<(B_ * TE_ / 8) + (B_ * TD_ / 8), 128>>>(enc, dec, Wa, Ua);

    dim3 grid(TD_ / DT_, B_);
    attn_kernel<<<grid, THREADS2, smem_bytes>>>(enc, Va, c_out, e_out);
}